// round 1
// baseline (speedup 1.0000x reference)
#include <cuda_runtime.h>
#include <cstddef>

// LoG = GaussianBlur(3,sigma=1) then Laplacian(ksize=9) + 1, clipped to [0,255].
// Fused as a single pass: composite 11x11 kernel = A(x)B(y) + B(x)A(y) with
//   A = gauss3 (*) smooth9   (11 taps, symmetric)
//   B = gauss3 (*) d2_9      (11 taps, symmetric)
// Reflect-101 padding of the input by 5 is exactly equivalent to the staged
// reflect-pad of the reference (symmetric kernels commute with reflect-101).

#define Hn 512
#define Wn 512
#define Cn 3
#define ROWB (Wn*Cn)          // 1536 floats per image row
#define TH 32                 // output rows per block
#define TWP 32                // output pixels per block
#define HALO 5
#define IN_H (TH + 2*HALO)    // 42
#define IN_WP (TWP + 2*HALO)  // 42 pixels per channel in smem
#define IN_PITCH (IN_WP + 2)  // 44
#define HP (TWP + 1)          // 33  (hA/hB pitch)
#define NTHREADS 384

// gauss3 = [g0, g1, g0], g1 = 1/(1+2e^{-1/2}), g0 = (1-g1)/2
// A = conv(gauss3, [1,8,28,56,70,56,28,8,1])
// B = conv(gauss3, [1,4,4,-4,-10,-4,4,4,1])
__device__ __forceinline__ void get_coeffs(float* cA, float* cB) {
    const float A0 = 0.27406862f,  A1 = 2.64441172f,  A2 = 11.56289206f,
                A3 = 30.19254896f, A4 = 52.16303932f, A5 = 62.32607864f;
    const float B0 = 0.27406862f,  B1 = 1.54813724f,  B2 = 3.17779414f,
                B3 = 1.80745104f,  B4 = -3.45186276f, B5 = -6.71117656f;
    cA[0]=A0; cA[1]=A1; cA[2]=A2; cA[3]=A3; cA[4]=A4; cA[5]=A5;
    cA[6]=A4; cA[7]=A3; cA[8]=A2; cA[9]=A1; cA[10]=A0;
    cB[0]=B0; cB[1]=B1; cB[2]=B2; cB[3]=B3; cB[4]=B4; cB[5]=B5;
    cB[6]=B4; cB[7]=B3; cB[8]=B2; cB[9]=B1; cB[10]=B0;
}

__device__ __forceinline__ int reflect101(int i, int n) {
    i = (i < 0) ? -i : i;
    return (i >= n) ? (2*n - 2 - i) : i;
}

__global__ void log_fused_kernel(const float* __restrict__ x,
                                 float* __restrict__ out) {
    extern __shared__ float smem[];
    float* in_s = smem;                              // [3][IN_H][IN_PITCH]
    float* hA_s = smem + 3 * IN_H * IN_PITCH;        // [3][IN_H][HP]
    float* hB_s = hA_s + 3 * IN_H * HP;              // [3][IN_H][HP]

    const int tid = threadIdx.x;
    const int h0  = blockIdx.y * TH;
    const int p0  = blockIdx.x * TWP;
    const size_t plane = (size_t)blockIdx.z * (size_t)(Hn * Wn * Cn);
    const float* xp = x + plane;

    float cA[11], cB[11];
    get_coeffs(cA, cB);

    // ---------- Phase 1: load (channel-deinterleave into smem, reflect-101) ----------
    {
        const int lf  = tid & 127;   // float column within the 126-wide strip
        const int lr0 = tid >> 7;    // 0..2
        if (lf < IN_WP * 3) {
            const int q = lf / 3;
            const int c = lf - q * 3;
            const int wp = reflect101(p0 - HALO + q, Wn);
            const int src_col = wp * 3 + c;
            float* dst = in_s + c * (IN_H * IN_PITCH) + q;
            #pragma unroll 1
            for (int r = lr0; r < IN_H; r += 3) {
                const int gh = reflect101(h0 - HALO + r, Hn);
                dst[r * IN_PITCH] = xp[(size_t)gh * ROWB + src_col];
            }
        }
    }
    __syncthreads();

    // ---------- Phase 2: horizontal 11-tap, two filters, 8-output sliding segs ----------
    // tasks: 3 channels * 42 rows * 4 segments = 504
    for (int s = tid; s < 3 * IN_H * 4; s += NTHREADS) {
        const int c   = s / (IN_H * 4);
        const int rem = s - c * (IN_H * 4);
        const int r   = rem >> 2;
        const int p   = (rem & 3) * 8;
        const float* src = in_s + c * (IN_H * IN_PITCH) + r * IN_PITCH + p;
        float v[18];
        #pragma unroll
        for (int i = 0; i < 18; i++) v[i] = src[i];
        float* dA = hA_s + c * (IN_H * HP) + r * HP + p;
        float* dB = hB_s + c * (IN_H * HP) + r * HP + p;
        #pragma unroll
        for (int j = 0; j < 8; j++) {
            float a = 0.f, b = 0.f;
            #pragma unroll
            for (int t = 0; t < 11; t++) {
                a = fmaf(cA[t], v[j + t], a);
                b = fmaf(cB[t], v[j + t], b);
            }
            dA[j] = a;
            dB[j] = b;
        }
    }
    __syncthreads();

    // ---------- Phase 3: vertical 11-tap, register window, 8 rows per thread ----------
    // 96 (p,c) columns * 4 row-chunks = 384 tasks = one per thread
    {
        const int col   = tid % 96;     // consecutive tid -> consecutive output floats
        const int chunk = tid / 96;     // 0..3
        const int p = col / 3;
        const int c = col - p * 3;
        const int r0 = chunk * 8;
        const float* sA = hA_s + c * (IN_H * HP) + r0 * HP + p;
        const float* sB = hB_s + c * (IN_H * HP) + r0 * HP + p;
        float vA[18], vB[18];
        #pragma unroll
        for (int i = 0; i < 18; i++) {
            vA[i] = sA[i * HP];
            vB[i] = sB[i * HP];
        }
        float* op = out + plane + (size_t)(h0 + r0) * ROWB + (p0 + p) * 3 + c;
        #pragma unroll
        for (int j = 0; j < 8; j++) {
            float acc = 1.0f;   // delta = 1
            #pragma unroll
            for (int t = 0; t < 11; t++) {
                acc = fmaf(cB[t], vA[j + t], acc);
                acc = fmaf(cA[t], vB[j + t], acc);
            }
            acc = fminf(fmaxf(acc, 0.0f), 255.0f);
            op[j * ROWB] = acc;
        }
    }
}

extern "C" void kernel_launch(void* const* d_in, const int* in_sizes, int n_in,
                              void* d_out, int out_size) {
    const float* x = (const float*)d_in[0];
    float* out = (float*)d_out;
    const int N = in_sizes[0] / (Hn * Wn * Cn);

    const int smem_bytes = (3 * IN_H * IN_PITCH + 2 * 3 * IN_H * HP) * (int)sizeof(float);
    cudaFuncSetAttribute(log_fused_kernel,
                         cudaFuncAttributeMaxDynamicSharedMemorySize, smem_bytes);

    dim3 grid(Wn / TWP, Hn / TH, N);   // (16, 16, 32)
    log_fused_kernel<<<grid, NTHREADS, smem_bytes>>>(x, out);
}

// round 2
// speedup vs baseline: 1.4574x; 1.4574x over previous
#include <cuda_runtime.h>
#include <cstddef>

// LoG = GaussianBlur(3,sigma=1) -> Laplacian(ksize=9) + 1, clip [0,255].
// Fused: composite 11x11 = A(x)B(y) + B(x)A(y), A = g3*S9, B = g3*D2_9.
// Reflect-101 pad of 5 on input == staged reflect pads (symmetric kernels).

#define Hn 512
#define Wn 512
#define ROWF 1536            // floats per image row (512*3)
#define TH 32                // output rows / block
#define TWP 32               // output pixels / block
#define HALO 5
#define IN_H 42              // TH + 2*HALO
#define IN_WP 42             // input pixels per channel in smem
#define IN_PITCH 43          // row pitch (floats), 43 % 32 = 11 -> conflict-free reads
#define CH_STRIDE 1813       // channel plane stride (42*43=1806 +7), == 21 mod 32
#define HP 33                // hA/hB row pitch
#define HB_PLANE 1387        // channel plane stride for hA/hB (42*33=1386 +1), == 11 mod 32
#define NTHREADS 512

__device__ __forceinline__ int reflect101(int i, int n) {
    i = (i < 0) ? -i : i;
    return (i >= n) ? (2 * n - 2 - i) : i;
}

__global__ __launch_bounds__(NTHREADS, 4)
void log_fused_kernel(const float* __restrict__ x, float* __restrict__ out) {
    extern __shared__ float smem[];
    float* in_s = smem;                         // 3 planes of [IN_H][IN_PITCH], stride CH_STRIDE
    float* hA_s = smem + 3 * CH_STRIDE;         // 3 planes of [IN_H][HP], stride HB_PLANE
    float* hB_s = hA_s + 3 * HB_PLANE;

    // Coefficients (A = gauss3 (*) smooth9, B = gauss3 (*) d2_9). Local const
    // arrays + full unroll -> folded to FFMA immediates.
    const float cA[11] = {
        0.274068619061f,  2.644411714f, 11.562892048f, 30.192548953f,
        52.163039333f,   62.326078667f, 52.163039333f, 30.192548953f,
        11.562892048f,    2.644411714f,  0.274068619061f };
    const float cB[11] = {
        0.274068619061f,  1.548137238f,  3.177794143f,  1.807451048f,
       -3.451862762f,    -6.711176571f, -3.451862762f,  1.807451048f,
        3.177794143f,     1.548137238f,  0.274068619061f };

    const int tid = threadIdx.x;
    const int h0  = blockIdx.y * TH;
    const int p0  = blockIdx.x * TWP;
    const size_t plane = (size_t)blockIdx.z * (size_t)(Hn * ROWF);
    const float* xp = x + plane;

    // ---------- Phase 1: gmem -> smem, channel-deinterleave, reflect-101 ----------
    {
        const int f  = tid & 127;   // float column in the 126-wide halo strip
        const int rg = tid >> 7;    // 0..3 row group
        if (f < IN_WP * 3) {
            const int q = f / 3;
            const int c = f - q * 3;
            const int wp = reflect101(p0 - HALO + q, Wn);
            const int src_col = wp * 3 + c;
            float* dst = in_s + c * CH_STRIDE + q;
            #pragma unroll 4
            for (int r = rg; r < IN_H; r += 4) {
                const int gh = reflect101(h0 - HALO + r, Hn);
                dst[r * IN_PITCH] = xp[(size_t)gh * ROWF + src_col];
            }
        }
    }
    __syncthreads();

    // ---------- Phase 2: horizontal 11-tap (A and B), streaming accumulators ----------
    // 3 ch * 42 rows * 4 eight-output segments = 504 tasks, one per thread.
    if (tid < 3 * IN_H * 4) {
        const int c   = tid / (IN_H * 4);
        const int rem = tid - c * (IN_H * 4);
        const int r   = rem >> 2;
        const int p   = (rem & 3) << 3;
        const float* src = in_s + c * CH_STRIDE + r * IN_PITCH + p;

        float aA[8], aB[8];
        #pragma unroll
        for (int j = 0; j < 8; j++) { aA[j] = 0.f; aB[j] = 0.f; }
        #pragma unroll
        for (int i = 0; i < 18; i++) {
            const float v = src[i];
            #pragma unroll
            for (int j = 0; j < 8; j++) {
                const int t = i - j;
                if (t >= 0 && t < 11) {
                    aA[j] = fmaf(cA[t], v, aA[j]);
                    aB[j] = fmaf(cB[t], v, aB[j]);
                }
            }
        }
        float* dA = hA_s + c * HB_PLANE + r * HP + p;
        float* dB = hB_s + c * HB_PLANE + r * HP + p;
        #pragma unroll
        for (int j = 0; j < 8; j++) { dA[j] = aA[j]; dB[j] = aB[j]; }
    }
    __syncthreads();

    // ---------- Phase 3: vertical 11-tap combine, streaming accumulators ----------
    // 96 output columns (32 px * 3 ch) * 4 chunks of 8 rows = 384 tasks.
    if (tid < 384) {
        const int col   = tid % 96;       // consecutive tid -> consecutive out floats
        const int chunk = tid / 96;       // 0..3
        const int p = col / 3;
        const int c = col - p * 3;
        const int r0 = chunk * 8;
        const float* sA = hA_s + c * HB_PLANE + r0 * HP + p;
        const float* sB = hB_s + c * HB_PLANE + r0 * HP + p;

        float acc[8];
        #pragma unroll
        for (int j = 0; j < 8; j++) acc[j] = 1.0f;   // delta = 1
        #pragma unroll
        for (int i = 0; i < 18; i++) {
            const float va = sA[i * HP];
            const float vb = sB[i * HP];
            #pragma unroll
            for (int j = 0; j < 8; j++) {
                const int t = i - j;
                if (t >= 0 && t < 11) {
                    acc[j] = fmaf(cB[t], va, acc[j]);
                    acc[j] = fmaf(cA[t], vb, acc[j]);
                }
            }
        }
        float* op = out + plane + (size_t)(h0 + r0) * ROWF + p0 * 3 + col;
        #pragma unroll
        for (int j = 0; j < 8; j++) {
            op[j * ROWF] = fminf(fmaxf(acc[j], 0.0f), 255.0f);
        }
    }
}

extern "C" void kernel_launch(void* const* d_in, const int* in_sizes, int n_in,
                              void* d_out, int out_size) {
    const float* x = (const float*)d_in[0];
    float* out = (float*)d_out;
    const int N = in_sizes[0] / (Hn * Wn * 3);

    const int smem_bytes = (3 * CH_STRIDE + 2 * 3 * HB_PLANE) * (int)sizeof(float);
    cudaFuncSetAttribute(log_fused_kernel,
                         cudaFuncAttributeMaxDynamicSharedMemorySize, smem_bytes);

    dim3 grid(Wn / TWP, Hn / TH, N);   // (16, 16, N)
    log_fused_kernel<<<grid, NTHREADS, smem_bytes>>>(x, out);
}

// round 3
// speedup vs baseline: 1.6909x; 1.1602x over previous
#include <cuda_runtime.h>
#include <cstddef>

// LoG = GaussianBlur(3,sigma=1) -> Laplacian(ksize=9) + 1, clip [0,255].
// Fused: composite 11x11 = A(x)B(y) + B(x)A(y), A = g3*S9, B = g3*D2_9.
// Reflect-101 pad of 5 on input == staged reflect pads (symmetric kernels).

#define Hn 512
#define Wn 512
#define ROWF 1536            // floats per image row (512*3)
#define TH 32
#define TWP 32
#define HALO 5
#define IN_H 42              // TH + 2*HALO
#define IN_WP 42
#define IN_PITCH 44          // 16B-aligned rows
#define IN_PLANE 1848        // 42*44
#define HPP 68               // interleaved (A,B) row pitch: 32*2 + 4 pad
#define HAB_PLANE 2864       // 42*68 = 2856, padded to mult of 16B
#define NTHREADS 512

__device__ __forceinline__ int reflect101(int i, int n) {
    i = (i < 0) ? -i : i;
    return (i >= n) ? (2 * n - 2 - i) : i;
}

__global__ __launch_bounds__(NTHREADS, 3)
void log_fused_kernel(const float* __restrict__ x, float* __restrict__ out) {
    extern __shared__ float smem[];
    float* in_s  = smem;                       // 3 planes [IN_H][IN_PITCH]
    float* hAB_s = smem + 3 * IN_PLANE;        // 3 planes [IN_H][HPP], (A,B) interleaved

    const float cA[11] = {
        0.274068619061f,  2.644411714f, 11.562892048f, 30.192548953f,
        52.163039333f,   62.326078667f, 52.163039333f, 30.192548953f,
        11.562892048f,    2.644411714f,  0.274068619061f };
    const float cB[11] = {
        0.274068619061f,  1.548137238f,  3.177794143f,  1.807451048f,
       -3.451862762f,    -6.711176571f, -3.451862762f,  1.807451048f,
        3.177794143f,     1.548137238f,  0.274068619061f };

    const int tid = threadIdx.x;
    const int h0  = blockIdx.y * TH;
    const int p0  = blockIdx.x * TWP;
    const size_t plane = (size_t)blockIdx.z * (size_t)(Hn * ROWF);
    const float* xp = x + plane;

    // ================= Phase 1: gmem -> smem (deinterleave, reflect-101) ======
    if (p0 != 0 && p0 != (Wn - TWP)) {
        // ---- interior-W fast path: float4 loads, no column reflect ----
        // float columns needed: fidx0 = (p0-5)*3 - 1 .. +127 (128 floats, 16B aligned)
        const int fidx0 = (p0 - HALO) * 3 - 1;
        const int col4  = tid & 31;
        int r = tid >> 5;                       // 0..15

        // lane l (0..3): off = 4*col4 + l - 1; valid iff 0 <= off < 126
        int qq[4], cc[4];
        bool val[4];
        #pragma unroll
        for (int l = 0; l < 4; l++) {
            int off = 4 * col4 + l - 1;
            val[l] = (off >= 0) && (off < IN_WP * 3);
            int o = val[l] ? off : 0;
            qq[l] = o / 3;
            cc[l] = o - 3 * qq[l];
        }
        const float4* gp = (const float4*)(xp + fidx0 + 4 * col4);

        #pragma unroll
        for (int k = 0; k < 3; k++) {
            if (r < IN_H) {
                const int gh = reflect101(h0 - HALO + r, Hn);
                float4 v = gp[gh * (ROWF / 4)];
                float vv[4] = {v.x, v.y, v.z, v.w};
                const int rb = r * IN_PITCH;
                #pragma unroll
                for (int l = 0; l < 4; l++) {
                    if (val[l]) in_s[cc[l] * IN_PLANE + rb + qq[l]] = vv[l];
                }
            }
            r += 16;
        }
    } else {
        // ---- border-W scalar path (reflect both dims) ----
        const int f  = tid & 127;
        const int rg = tid >> 7;                // 0..3
        if (f < IN_WP * 3) {
            const int q = f / 3;
            const int c = f - q * 3;
            const int wp = reflect101(p0 - HALO + q, Wn);
            const int src_col = wp * 3 + c;
            float* dst = in_s + c * IN_PLANE + q;
            #pragma unroll 4
            for (int r = rg; r < IN_H; r += 4) {
                const int gh = reflect101(h0 - HALO + r, Hn);
                dst[r * IN_PITCH] = xp[(size_t)gh * ROWF + src_col];
            }
        }
    }
    __syncthreads();

    // ========== Phase 2: horizontal 11-tap (A and B), vectorized smem ========
    // 3 ch * 42 rows * 4 eight-output segments = 504 tasks.
    if (tid < 3 * IN_H * 4) {
        const int c   = tid / (IN_H * 4);
        const int rem = tid - c * (IN_H * 4);
        const int r   = rem >> 2;
        const int p   = (rem & 3) << 3;
        const float* src = in_s + c * IN_PLANE + r * IN_PITCH + p;

        float aA[8], aB[8];
        #pragma unroll
        for (int j = 0; j < 8; j++) { aA[j] = 0.f; aB[j] = 0.f; }

        // 18-float window: 4x float4 + 1x float2, streamed into accumulators
        #pragma unroll
        for (int ib = 0; ib < 4; ib++) {
            float4 v4 = *(const float4*)(src + 4 * ib);
            float vs[4] = {v4.x, v4.y, v4.z, v4.w};
            #pragma unroll
            for (int s = 0; s < 4; s++) {
                const int i = 4 * ib + s;
                const float v = vs[s];
                #pragma unroll
                for (int j = 0; j < 8; j++) {
                    const int t = i - j;
                    if (t >= 0 && t < 11) {
                        aA[j] = fmaf(cA[t], v, aA[j]);
                        aB[j] = fmaf(cB[t], v, aB[j]);
                    }
                }
            }
        }
        {
            float2 v2 = *(const float2*)(src + 16);
            float vs[2] = {v2.x, v2.y};
            #pragma unroll
            for (int s = 0; s < 2; s++) {
                const int i = 16 + s;
                const float v = vs[s];
                #pragma unroll
                for (int j = 0; j < 8; j++) {
                    const int t = i - j;
                    if (t >= 0 && t < 11) {
                        aA[j] = fmaf(cA[t], v, aA[j]);
                        aB[j] = fmaf(cB[t], v, aB[j]);
                    }
                }
            }
        }

        // interleaved (A,B) pairs -> 4x STS.128
        float4* d = (float4*)(hAB_s + c * HAB_PLANE + r * HPP + 2 * p);
        d[0] = make_float4(aA[0], aB[0], aA[1], aB[1]);
        d[1] = make_float4(aA[2], aB[2], aA[3], aB[3]);
        d[2] = make_float4(aA[4], aB[4], aA[5], aB[5]);
        d[3] = make_float4(aA[6], aB[6], aA[7], aB[7]);
    }
    __syncthreads();

    // ========== Phase 3: vertical 11-tap combine, LDS.64 paired reads ========
    // 96 output columns (32 px * 3 ch) * 4 chunks of 8 rows = 384 tasks.
    if (tid < 384) {
        const int col   = tid % 96;
        const int chunk = tid / 96;
        const int p = col / 3;
        const int c = col - p * 3;
        const int r0 = chunk * 8;
        const float2* s = (const float2*)(hAB_s + c * HAB_PLANE + r0 * HPP + 2 * p);

        float acc[8];
        #pragma unroll
        for (int j = 0; j < 8; j++) acc[j] = 1.0f;     // delta = 1

        #pragma unroll
        for (int i = 0; i < 18; i++) {
            float2 vab = s[i * (HPP / 2)];
            #pragma unroll
            for (int j = 0; j < 8; j++) {
                const int t = i - j;
                if (t >= 0 && t < 11) {
                    acc[j] = fmaf(cB[t], vab.x, acc[j]);
                    acc[j] = fmaf(cA[t], vab.y, acc[j]);
                }
            }
        }
        float* op = out + plane + (size_t)(h0 + r0) * ROWF + p0 * 3 + col;
        #pragma unroll
        for (int j = 0; j < 8; j++) {
            op[j * ROWF] = fminf(fmaxf(acc[j], 0.0f), 255.0f);
        }
    }
}

extern "C" void kernel_launch(void* const* d_in, const int* in_sizes, int n_in,
                              void* d_out, int out_size) {
    const float* x = (const float*)d_in[0];
    float* out = (float*)d_out;
    const int N = in_sizes[0] / (Hn * Wn * 3);

    const int smem_bytes = (3 * IN_PLANE + 3 * HAB_PLANE) * (int)sizeof(float);
    cudaFuncSetAttribute(log_fused_kernel,
                         cudaFuncAttributeMaxDynamicSharedMemorySize, smem_bytes);

    dim3 grid(Wn / TWP, Hn / TH, N);   // (16, 16, N)
    log_fused_kernel<<<grid, NTHREADS, smem_bytes>>>(x, out);
}